// round 8
// baseline (speedup 1.0000x reference)
#include <cuda_runtime.h>
#include <cstddef>

#define B_    256
#define T_    500
#define NIN_  128
#define NH_   512
#define NO_   64

#define PS      20                       // partial buffer pad (floats)
#define HS_FL   (NH_ * 16)               // 8192 floats per half h-buffer
#define PART_FL (16 * 32 * PS)           // 10240 floats
#define REC_SMEM 122880                  // 120 KB -> forces 1 CTA/SM (2x120 > 227KB)

// ---------------------------------------------------------------------------
// Device scratch (no runtime allocation allowed)
// ---------------------------------------------------------------------------
__device__ __align__(16) float g_h[2 * NH_ * B_];   // ping-pong hidden, k-major [k][b]
__device__ __align__(16) float g_bias[NH_];         // b_ih + b_hh
__device__ unsigned g_flag[2 * 8 * 32];             // [half][gb] flag counters, padded

// ---------------------------------------------------------------------------
// f32x2 packed FMA helpers
// ---------------------------------------------------------------------------
__device__ __forceinline__ unsigned long long pack2(float lo, float hi) {
    unsigned long long r;
    asm("mov.b64 %0, {%1, %2};" : "=l"(r) : "f"(lo), "f"(hi));
    return r;
}
__device__ __forceinline__ void fma2(unsigned long long& d,
                                     unsigned long long a, unsigned long long b) {
    asm("fma.rn.f32x2 %0, %1, %2, %0;" : "+l"(d) : "l"(a), "l"(b));
}
__device__ __forceinline__ float2 unpack2(unsigned long long v) {
    float2 f;
    asm("mov.b64 {%0, %1}, %2;" : "=f"(f.x), "=f"(f.y) : "l"(v));
    return f;
}

union U4 { float4 v; unsigned long long p[2]; };

// ---------------------------------------------------------------------------
// Init: transpose h0 into g_h slot 0 (k-major), fold biases, reset flags.
// <<<NH_, B_>>>
// ---------------------------------------------------------------------------
__global__ void init_kernel(const float* __restrict__ h0,
                            const float* __restrict__ b_ih,
                            const float* __restrict__ b_hh) {
    int k = blockIdx.x;
    int b = threadIdx.x;
    g_h[(size_t)k * B_ + b] = h0[(size_t)b * NH_ + k];
    if (b == 0) g_bias[k] = b_ih[k] + b_hh[k];
    if (k == 0 && b < 16) g_flag[b * 32] = 0u;
}

// ---------------------------------------------------------------------------
// C[m][c] = sum_k A[m][k]*Bm[c][k] + bias[c]
// 128x64 tile, K-chunks of 32, 8x4 micro-tile per thread, f32x2 FMAs.
// ---------------------------------------------------------------------------
__global__ __launch_bounds__(256)
void gemm_bias_kernel(const float* __restrict__ A, const float* __restrict__ Bm,
                      const float* __restrict__ bias, float* __restrict__ C,
                      int K, int Ntot, int bias_mode) {
    __shared__ float xs[32][128];
    __shared__ float ws[32][64];

    const int tid = threadIdx.x;
    const int m0  = blockIdx.x * 128;
    const int c0  = blockIdx.y * 64;
    const int tx  = tid & 15;
    const int ty  = tid >> 4;

    const int arow = tid & 127, akq = tid >> 7;
    const int bcol = tid & 63,  bkh = tid >> 6;

    unsigned long long acc[16];
#pragma unroll
    for (int i = 0; i < 16; i++) acc[i] = 0ull;

    for (int kc = 0; kc < K; kc += 32) {
#pragma unroll
        for (int i = 0; i < 4; i++) {
            int kk = akq * 16 + i * 4;
            float4 v = *(const float4*)(A + (size_t)(m0 + arow) * K + kc + kk);
            xs[kk + 0][arow] = v.x; xs[kk + 1][arow] = v.y;
            xs[kk + 2][arow] = v.z; xs[kk + 3][arow] = v.w;
        }
#pragma unroll
        for (int i = 0; i < 2; i++) {
            int kk = bkh * 8 + i * 4;
            float4 v = *(const float4*)(Bm + (size_t)(c0 + bcol) * K + kc + kk);
            ws[kk + 0][bcol] = v.x; ws[kk + 1][bcol] = v.y;
            ws[kk + 2][bcol] = v.z; ws[kk + 3][bcol] = v.w;
        }
        __syncthreads();

#pragma unroll
        for (int kk = 0; kk < 32; kk++) {
            U4 a0, a1, b4;
            a0.v = *(const float4*)(&xs[kk][8 * ty]);
            a1.v = *(const float4*)(&xs[kk][8 * ty + 4]);
            b4.v = *(const float4*)(&ws[kk][4 * tx]);
            unsigned long long s0 = pack2(b4.v.x, b4.v.x);
            unsigned long long s1 = pack2(b4.v.y, b4.v.y);
            unsigned long long s2 = pack2(b4.v.z, b4.v.z);
            unsigned long long s3 = pack2(b4.v.w, b4.v.w);
            fma2(acc[0],  a0.p[0], s0); fma2(acc[1],  a0.p[1], s0);
            fma2(acc[2],  a1.p[0], s0); fma2(acc[3],  a1.p[1], s0);
            fma2(acc[4],  a0.p[0], s1); fma2(acc[5],  a0.p[1], s1);
            fma2(acc[6],  a1.p[0], s1); fma2(acc[7],  a1.p[1], s1);
            fma2(acc[8],  a0.p[0], s2); fma2(acc[9],  a0.p[1], s2);
            fma2(acc[10], a1.p[0], s2); fma2(acc[11], a1.p[1], s2);
            fma2(acc[12], a0.p[0], s3); fma2(acc[13], a0.p[1], s3);
            fma2(acc[14], a1.p[0], s3); fma2(acc[15], a1.p[1], s3);
        }
        __syncthreads();
    }

    const float* bp = bias_mode ? g_bias : bias;
    float4 bv = *(const float4*)(bp + c0 + 4 * tx);

#pragma unroll
    for (int i = 0; i < 4; i++) {
        float2 p0 = unpack2(acc[0 * 4 + i]);
        float2 p1 = unpack2(acc[1 * 4 + i]);
        float2 p2 = unpack2(acc[2 * 4 + i]);
        float2 p3 = unpack2(acc[3 * 4 + i]);
        float4 lo = make_float4(p0.x + bv.x, p1.x + bv.y, p2.x + bv.z, p3.x + bv.w);
        float4 hi = make_float4(p0.y + bv.x, p1.y + bv.y, p2.y + bv.z, p3.y + bv.w);
        size_t r0 = (size_t)(m0 + 8 * ty + 2 * i) * Ntot + c0 + 4 * tx;
        *(float4*)(C + r0)        = lo;
        *(float4*)(C + r0 + Ntot) = hi;
    }
}

// ---------------------------------------------------------------------------
// Persistent recurrence. 128 CTAs x 256 threads. CTA(gb,cg): 32 rows x 32 cols,
// processed as two pipelined 16-row halves with independent flags.
// W_hh slice pre-packed f32x2 in registers (k-strided per thread).
// ---------------------------------------------------------------------------
__global__ __launch_bounds__(256, 1)
void rnn_rec_kernel(const float* __restrict__ W_hh, const float* __restrict__ alpha,
                    float* __restrict__ outH, float* __restrict__ outF) {
    extern __shared__ float sm[];
    float* part = sm + 2 * HS_FL;

    const int tid = threadIdx.x;
    const int gb  = blockIdx.x & 7;
    const int cg  = blockIdx.x >> 3;

    // ---- compute role: thread (c2,g) owns cols {cg*32+2c2, +1}, k = g+16j ----
    const int c2 = tid & 15, g = tid >> 4;
    unsigned long long wp0[32], wp1[32];
    {
        const float* w0 = W_hh + (size_t)(cg * 32 + 2 * c2) * NH_;
#pragma unroll
        for (int j = 0; j < 32; j++) {
            float a0 = w0[g + 16 * j];
            float a1 = w0[NH_ + g + 16 * j];
            wp0[j] = pack2(a0, a0);
            wp1[j] = pack2(a1, a1);
        }
    }

    // ---- loader role ----
    const int lq = tid & 3, lk = tid >> 2;

    // ---- reduce role (tid < 128): row rrow, col quad rcq (4 cols) ----
    const bool red = tid < 128;
    const int rrow = tid & 15, rcq = (tid >> 4) & 7;
    float al0 = 0, al1 = 0, al2 = 0, al3 = 0, om0 = 0, om1 = 0, om2 = 0, om3 = 0;
    if (red) {
        float4 av = *(const float4*)(alpha + cg * 32 + 4 * rcq);
        al0 = av.x; al1 = av.y; al2 = av.z; al3 = av.w;
        om0 = 1.f - av.x; om1 = 1.f - av.y; om2 = 1.f - av.z; om3 = 1.f - av.w;
    }

    for (int t = 0; t < T_; t++) {
        const float* hsrc = g_h + (size_t)(t & 1) * NH_ * B_;
        float*       hdst = g_h + (size_t)((t + 1) & 1) * NH_ * B_;

#pragma unroll 1
        for (int half = 0; half < 2; half++) {
            float* hsb = sm + half * HS_FL;
            unsigned* flg = &g_flag[(half * 8 + gb) * 32];

            // 1) wait for all 16 cg-CTAs' previous-step writes of this half
            if (t > 0) {
                if (tid == 0) {
                    unsigned target = 16u * (unsigned)t, v;
                    do {
                        asm volatile("ld.global.acquire.gpu.u32 %0, [%1];"
                                     : "=r"(v) : "l"(flg));
                    } while (v < target);
                }
                __syncthreads();
            }

            // 2) load h tile (512 k x 16 b) into smem; prefetch pre from outH
#pragma unroll
            for (int i = 0; i < 8; i++) {
                int k = lk + 64 * i;
                float4 v = __ldcg((const float4*)(hsrc + (size_t)k * B_ +
                                                  gb * 32 + half * 16 + 4 * lq));
                *(float4*)(hsb + k * 16 + 4 * lq) = v;
            }
            float4 pre = make_float4(0, 0, 0, 0);
            size_t haddr = 0;
            if (red) {
                haddr = ((size_t)(gb * 32 + half * 16 + rrow) * T_ + t) * NH_ +
                        cg * 32 + 4 * rcq;
                pre = __ldcs((const float4*)(outH + haddr));
            }
            __syncthreads();

            // 3) partial GEMM: 32 k per thread, 2 cols, 16 rows
            unsigned long long a0[8], a1[8];
#pragma unroll
            for (int i = 0; i < 8; i++) { a0[i] = 0ull; a1[i] = 0ull; }
#pragma unroll
            for (int j = 0; j < 32; j++) {
                const float* row = hsb + (g + 16 * j) * 16;
                U4 h0, h1, h2, h3;
                h0.v = *(const float4*)(row);
                h1.v = *(const float4*)(row + 4);
                h2.v = *(const float4*)(row + 8);
                h3.v = *(const float4*)(row + 12);
                fma2(a0[0], h0.p[0], wp0[j]); fma2(a0[1], h0.p[1], wp0[j]);
                fma2(a0[2], h1.p[0], wp0[j]); fma2(a0[3], h1.p[1], wp0[j]);
                fma2(a0[4], h2.p[0], wp0[j]); fma2(a0[5], h2.p[1], wp0[j]);
                fma2(a0[6], h3.p[0], wp0[j]); fma2(a0[7], h3.p[1], wp0[j]);
                fma2(a1[0], h0.p[0], wp1[j]); fma2(a1[1], h0.p[1], wp1[j]);
                fma2(a1[2], h1.p[0], wp1[j]); fma2(a1[3], h1.p[1], wp1[j]);
                fma2(a1[4], h2.p[0], wp1[j]); fma2(a1[5], h2.p[1], wp1[j]);
                fma2(a1[6], h3.p[0], wp1[j]); fma2(a1[7], h3.p[1], wp1[j]);
            }
            {
                float* pb0 = part + (size_t)(g * 32 + 2 * c2) * PS;
                float* pb1 = pb0 + PS;
#pragma unroll
                for (int q = 0; q < 4; q++) {
                    float2 lo = unpack2(a0[2 * q]);
                    float2 hi = unpack2(a0[2 * q + 1]);
                    *(float4*)(pb0 + 4 * q) = make_float4(lo.x, lo.y, hi.x, hi.y);
                    lo = unpack2(a1[2 * q]);
                    hi = unpack2(a1[2 * q + 1]);
                    *(float4*)(pb1 + 4 * q) = make_float4(lo.x, lo.y, hi.x, hi.y);
                }
            }
            __syncthreads();

            // 4) reduce 16 k-groups, add pre, relu, leaky update, writes
            if (red) {
                float s0 = 0.f, s1 = 0.f, s2 = 0.f, s3 = 0.f;
                const float* pb = part + (size_t)(4 * rcq) * PS + rrow;
#pragma unroll
                for (int g2 = 0; g2 < 16; g2++) {
                    const float* p = pb + (size_t)g2 * (32 * PS);
                    s0 += p[0];
                    s1 += p[PS];
                    s2 += p[2 * PS];
                    s3 += p[3 * PS];
                }
                float c0 = fmaxf(s0 + pre.x, 0.f);
                float c1 = fmaxf(s1 + pre.y, 0.f);
                float c2v = fmaxf(s2 + pre.z, 0.f);
                float c3 = fmaxf(s3 + pre.w, 0.f);
                const int kc = cg * 32 + 4 * rcq;
                float h0v = om0 * hsb[(kc + 0) * 16 + rrow] + al0 * c0;
                float h1v = om1 * hsb[(kc + 1) * 16 + rrow] + al1 * c1;
                float h2v = om2 * hsb[(kc + 2) * 16 + rrow] + al2 * c2v;
                float h3v = om3 * hsb[(kc + 3) * 16 + rrow] + al3 * c3;
                float4 hn = make_float4(h0v, h1v, h2v, h3v);
                *(float4*)(outH + haddr) = hn;               // hidden_list
                const int brow = gb * 32 + half * 16 + rrow;
                if (t < T_ - 1) {
                    __stcg(hdst + (size_t)(kc + 0) * B_ + brow, h0v);
                    __stcg(hdst + (size_t)(kc + 1) * B_ + brow, h1v);
                    __stcg(hdst + (size_t)(kc + 2) * B_ + brow, h2v);
                    __stcg(hdst + (size_t)(kc + 3) * B_ + brow, h3v);
                } else {
                    *(float4*)(outF + (size_t)brow * NH_ + kc) = hn;
                }
            }

            // 5) release this half's flag
            if (t < T_ - 1) {
                __syncthreads();
                if (tid == 0) {
                    __threadfence();
                    atomicAdd(flg, 1u);
                }
            }
        }
    }
}

// ---------------------------------------------------------------------------
extern "C" void kernel_launch(void* const* d_in, const int* in_sizes, int n_in,
                              void* d_out, int out_size) {
    const float* x     = (const float*)d_in[0];   // [B,T,128]
    const float* h0    = (const float*)d_in[1];   // [B,512]
    const float* Wih   = (const float*)d_in[2];   // [512,128]
    const float* Whh   = (const float*)d_in[3];   // [512,512]
    const float* bih   = (const float*)d_in[4];   // [512]
    const float* bhh   = (const float*)d_in[5];   // [512]
    const float* Wout  = (const float*)d_in[6];   // [64,512]
    const float* bout  = (const float*)d_in[7];   // [64]
    const float* alpha = (const float*)d_in[8];   // [512]

    float* out  = (float*)d_out;
    float* outH = out;                                   // hidden_list [B,T,512]
    float* outO = out + (size_t)B_ * T_ * NH_;           // output_list [B,T,64]
    float* outF = outO + (size_t)B_ * T_ * NO_;          // h_final     [B,512]

    cudaFuncSetAttribute(rnn_rec_kernel,
                         cudaFuncAttributeMaxDynamicSharedMemorySize, REC_SMEM);

    // 1) init hidden transpose + bias fold + flag reset
    init_kernel<<<NH_, B_>>>(h0, bih, bhh);

    // 2) pre = x @ W_ih^T + (b_ih + b_hh), into hidden_list region (in-place)
    gemm_bias_kernel<<<dim3((B_ * T_) / 128, NH_ / 64), 256>>>(
        x, Wih, nullptr, outH, NIN_, NH_, 1);

    // 3) 500-step recurrence, persistent, pipelined halves
    rnn_rec_kernel<<<128, 256, REC_SMEM>>>(Whh, alpha, outH, outF);

    // 4) output_list = hidden_list @ W_out^T + b_out
    gemm_bias_kernel<<<dim3((B_ * T_) / 128, NO_ / 64), 256>>>(
        outH, Wout, bout, outO, NH_, NO_, 0);
}